// round 1
// baseline (speedup 1.0000x reference)
#include <cuda_runtime.h>

#define TT 1024
#define BB 32
#define II 512
#define HH 512
#define GG 2048   // 4*H

// Scratch: gates_x in [t][g][b] layout (scan-friendly: lane=b coalesced)
__device__ float g_gates[(size_t)TT * GG * BB];
__device__ unsigned int g_bar_count;
__device__ unsigned int g_bar_gen;

// ---------------------------------------------------------------------------
// Kernel 1: gates_x[t,b,g] = sum_i input[t,b,i] * W_ih[g,i] + b_ih[g] + b_hh[g]
// A = input [M=T*B, K=512] row-major, W = W_ih [G=2048, K=512] row-major (NT gemm)
// ---------------------------------------------------------------------------
#define BM 128
#define BN 128
#define BK 16
#define LDP 132   // padded shared row pitch (floats), %4==0 so float4 stays aligned

__global__ __launch_bounds__(256) void gemm_input(
    const float* __restrict__ A, const float* __restrict__ W,
    const float* __restrict__ b_ih, const float* __restrict__ b_hh)
{
    __shared__ __align__(16) float As[BK * LDP];
    __shared__ __align__(16) float Bs[BK * LDP];
    const int tid = threadIdx.x;
    const int m0 = blockIdx.y * BM;
    const int n0 = blockIdx.x * BN;
    const int tm = (tid >> 4) * 8;
    const int tn = (tid & 15) * 8;

    float acc[8][8];
#pragma unroll
    for (int i = 0; i < 8; i++)
#pragma unroll
        for (int j = 0; j < 8; j++) acc[i][j] = 0.f;

    for (int k0 = 0; k0 < II; k0 += BK) {
#pragma unroll
        for (int i = 0; i < 2; i++) {
            int f   = tid + i * 256;      // 0..511
            int row = f >> 2;             // 0..127
            int kq  = (f & 3) * 4;        // 0,4,8,12
            float4 va = *(const float4*)(A + (size_t)(m0 + row) * II + k0 + kq);
            As[(kq + 0) * LDP + row] = va.x;
            As[(kq + 1) * LDP + row] = va.y;
            As[(kq + 2) * LDP + row] = va.z;
            As[(kq + 3) * LDP + row] = va.w;
            float4 vb = *(const float4*)(W + (size_t)(n0 + row) * II + k0 + kq);
            Bs[(kq + 0) * LDP + row] = vb.x;
            Bs[(kq + 1) * LDP + row] = vb.y;
            Bs[(kq + 2) * LDP + row] = vb.z;
            Bs[(kq + 3) * LDP + row] = vb.w;
        }
        __syncthreads();
#pragma unroll
        for (int k = 0; k < BK; k++) {
            float a[8], bb[8];
            *(float4*)&a[0]  = *(float4*)&As[k * LDP + tm];
            *(float4*)&a[4]  = *(float4*)&As[k * LDP + tm + 4];
            *(float4*)&bb[0] = *(float4*)&Bs[k * LDP + tn];
            *(float4*)&bb[4] = *(float4*)&Bs[k * LDP + tn + 4];
#pragma unroll
            for (int i = 0; i < 8; i++)
#pragma unroll
                for (int j = 0; j < 8; j++) acc[i][j] += a[i] * bb[j];
        }
        __syncthreads();
    }

    float bj[8];
#pragma unroll
    for (int j = 0; j < 8; j++) {
        int g = n0 + tn + j;
        bj[j] = b_ih[g] + b_hh[g];
    }
#pragma unroll
    for (int i = 0; i < 8; i++) {
        int m = m0 + tm + i;
        int t = m >> 5, b = m & 31;
        size_t base = ((size_t)t * GG) * BB + (size_t)b;
#pragma unroll
        for (int j = 0; j < 8; j++) {
            int g = n0 + tn + j;
            g_gates[base + (size_t)g * BB] = acc[i][j] + bj[j];
        }
    }
}

// ---------------------------------------------------------------------------
// Kernel 2: persistent LSTM scan. 128 blocks x 256 threads, custom grid barrier.
// Block bk owns h-columns j0..j0+3 (j0 = 4*bk) -> gate columns {gate*512 + j0+u}.
// W_hh slice (16 x 512 = 32KB) lives in shared for the whole kernel.
// h_prev (32 x 512, padded pitch 516 -> conflict-free LDS.128) reloaded per step.
// Thread (b,u) (tid<128) computes all 4 gates of one h-column.
// ---------------------------------------------------------------------------
#define NBLK 128
#define NTHR 256
#define HP 516

__device__ __forceinline__ void grid_barrier()
{
    __syncthreads();
    if (threadIdx.x == 0) {
        unsigned gen = *((volatile unsigned*)&g_bar_gen);
        __threadfence();
        if (atomicAdd(&g_bar_count, 1u) == NBLK - 1) {
            g_bar_count = 0;
            __threadfence();
            atomicAdd(&g_bar_gen, 1u);   // release
        } else {
            while (*((volatile unsigned*)&g_bar_gen) == gen) { }
        }
        __threadfence();
    }
    __syncthreads();
}

__global__ __launch_bounds__(NTHR) void lstm_scan(
    const float* __restrict__ h0, const float* __restrict__ c0,
    const float* __restrict__ W_hh, float* __restrict__ out, int out_size)
{
    extern __shared__ __align__(16) float smem[];
    float* W_sh = smem;                // 16*512 floats (32 KB)
    float* h_sh = smem + 16 * 512;     // 32*HP floats (~66 KB)

    const int tid = threadIdx.x;
    const int j0  = blockIdx.x * 4;

    // Preload this block's W_hh slice once (static across all timesteps).
    for (int f4 = tid; f4 < 16 * 128; f4 += NTHR) {
        int c = f4 >> 7, k4 = f4 & 127;
        int gcol = (c >> 2) * HH + j0 + (c & 3);   // c = (gate<<2)|u
        *(float4*)&W_sh[c * 512 + k4 * 4] =
            *(const float4*)&W_hh[(size_t)gcol * HH + k4 * 4];
    }

    const int u = tid >> 5;    // warp id 0..7; compute warps use u<4
    const int b = tid & 31;
    float creg = 0.f, hreg = 0.f;
    if (tid < 128) creg = c0[b * HH + j0 + u];

    float* outputs = out;   // [T][B][H] region of d_out

    for (int t = 0; t < TT; t++) {
        const float* hp = (t == 0) ? h0 : (outputs + (size_t)(t - 1) * BB * HH);
        // Cooperative load of full h_prev into shared (transposed-pitch layout).
#pragma unroll
        for (int r = 0; r < 16; r++) {
            int f4 = r * NTHR + tid;     // 0..4095
            int b2 = f4 >> 7, k4 = f4 & 127;
            *(float4*)&h_sh[b2 * HP + k4 * 4] =
                *(const float4*)&hp[b2 * HH + k4 * 4];
        }
        __syncthreads();   // also covers W_sh preload on t==0

        if (tid < 128) {
            const float* gx = g_gates + (size_t)t * GG * BB;
            float ai = gx[(size_t)(0 * HH + j0 + u) * BB + b];
            float af = gx[(size_t)(1 * HH + j0 + u) * BB + b];
            float ag = gx[(size_t)(2 * HH + j0 + u) * BB + b];
            float ao = gx[(size_t)(3 * HH + j0 + u) * BB + b];

            const float4* hv = (const float4*)&h_sh[b * HP];
            const float4* wi = (const float4*)&W_sh[(u + 0)  * 512];
            const float4* wf = (const float4*)&W_sh[(u + 4)  * 512];
            const float4* wg = (const float4*)&W_sh[(u + 8)  * 512];
            const float4* wo = (const float4*)&W_sh[(u + 12) * 512];
#pragma unroll 8
            for (int k4 = 0; k4 < 128; k4++) {
                float4 h4 = hv[k4];
                float4 w;
                w = wi[k4]; ai += h4.x * w.x; ai += h4.y * w.y; ai += h4.z * w.z; ai += h4.w * w.w;
                w = wf[k4]; af += h4.x * w.x; af += h4.y * w.y; af += h4.z * w.z; af += h4.w * w.w;
                w = wg[k4]; ag += h4.x * w.x; ag += h4.y * w.y; ag += h4.z * w.z; ag += h4.w * w.w;
                w = wo[k4]; ao += h4.x * w.x; ao += h4.y * w.y; ao += h4.z * w.z; ao += h4.w * w.w;
            }
            float ig  = 1.f / (1.f + __expf(-ai));
            float fg  = 1.f / (1.f + __expf(-af));
            float gg2 = tanhf(ag);
            float og  = 1.f / (1.f + __expf(-ao));
            creg = fg * creg + ig * gg2;
            hreg = og * tanhf(creg);
            outputs[(size_t)t * BB * HH + (size_t)b * HH + j0 + u] = hreg;
        }
        grid_barrier();   // makes h_t globally visible; protects h_sh reuse
    }

    // Tail: h_f then c_f appended after outputs (guard in case out omits them).
    if (tid < 128) {
        size_t off = (size_t)TT * BB * HH;
        if ((size_t)out_size >= off + 2u * BB * HH) {
            out[off + (size_t)b * HH + j0 + u]           = hreg;
            out[off + BB * HH + (size_t)b * HH + j0 + u] = creg;
        }
    }
}

// ---------------------------------------------------------------------------
extern "C" void kernel_launch(void* const* d_in, const int* in_sizes, int n_in,
                              void* d_out, int out_size)
{
    const float* input = (const float*)d_in[0];
    const float* h0    = (const float*)d_in[1];
    const float* c0    = (const float*)d_in[2];
    const float* W_ih  = (const float*)d_in[3];
    const float* W_hh  = (const float*)d_in[4];
    const float* b_ih  = (const float*)d_in[5];
    const float* b_hh  = (const float*)d_in[6];

    size_t smem = (size_t)(16 * 512 + 32 * HP) * sizeof(float);  // ~98.8 KB
    cudaFuncSetAttribute(lstm_scan, cudaFuncAttributeMaxDynamicSharedMemorySize,
                         (int)smem);

    dim3 g1(GG / BN, (TT * BB) / BM);   // 16 x 256 blocks
    gemm_input<<<g1, 256>>>(input, W_ih, b_ih, b_hh);
    lstm_scan<<<NBLK, NTHR, smem>>>(h0, c0, W_hh, (float*)d_out, out_size);
}